// round 14
// baseline (speedup 1.0000x reference)
#include <cuda_runtime.h>

#define DIM  480
#define WPB  8          // warps (rows) per block
#define SEGV 88         // segment-region float4 per row

__global__ __launch_bounds__(WPB * 32) void eqln_kernel(
    const float* __restrict__ x,
    const float* __restrict__ w,
    const float* __restrict__ bias,
    float* __restrict__ out,
    int n)
{
    __shared__ float4 sres4[WPB][SEGV];    // staged RESULTS only (coalesced store)

    const int warp = threadIdx.x >> 5;
    const int lane = threadIdx.x & 31;
    const int row  = blockIdx.x * WPB + warp;
    if (row >= n) return;

    float* sres = reinterpret_cast<float*>(sres4[warp]);
    const size_t off = (size_t)row * DIM;
    const float* src = x + off;
    float* dst       = out + off;

    // ---- front-batch ALL loads (9 per lane; lane-private segment data) ----
    float4 q = __ldcs(reinterpret_cast<const float4*>(src) + lane);   // floats 4l..4l+3

    // 3-seg region: lane owns segs 2l,2l+1 = floats 128+6l..+5 (8B-aligned float2 x3)
    const float2* p3 = reinterpret_cast<const float2*>(src + 128 + 6 * lane);
    float2 t0 = __ldcs(p3 + 0);
    float2 t1 = __ldcs(p3 + 1);
    float2 t2 = __ldcs(p3 + 2);

    // 5-seg region: lane owns seg l = floats 320+5l..+4
    const float* p5 = src + 320 + 5 * lane;
    float u0 = __ldcs(p5 + 0);
    float u1 = __ldcs(p5 + 1);
    float u2 = __ldcs(p5 + 2);
    float u3 = __ldcs(p5 + 3);
    float u4 = __ldcs(p5 + 4);

    // ---- segment norms in registers ----
    {   // seg 2l: t0.x t0.y t1.x
        float m  = (t0.x + t0.y + t1.x) * (1.0f / 3.0f);
        float da = t0.x - m, db = t0.y - m, dc = t1.x - m;
        float rv = rsqrtf((da * da + db * db + dc * dc) * (1.0f / 3.0f) + 1e-5f);
        t0.x = da * rv; t0.y = db * rv; t1.x = dc * rv;
    }
    {   // seg 2l+1: t1.y t2.x t2.y
        float m  = (t1.y + t2.x + t2.y) * (1.0f / 3.0f);
        float da = t1.y - m, db = t2.x - m, dc = t2.y - m;
        float rv = rsqrtf((da * da + db * db + dc * dc) * (1.0f / 3.0f) + 1e-5f);
        t1.y = da * rv; t2.x = db * rv; t2.y = dc * rv;
    }
    {   // seg l of 5
        float m  = (u0 + u1 + u2 + u3 + u4) * 0.2f;
        float da = u0 - m, db = u1 - m, dc = u2 - m, dd = u3 - m, de = u4 - m;
        float rv = rsqrtf((da * da + db * db + dc * dc + dd * dd + de * de) * 0.2f + 1e-5f);
        u0 = da * rv; u1 = db * rv; u2 = dc * rv; u3 = dd * rv; u4 = de * rv;
    }

    // ---- stage results into smem (conflict-light) ----
    {
        float2* r3 = reinterpret_cast<float2*>(sres + 6 * lane);
        r3[0] = t0; r3[1] = t1; r3[2] = t2;
        float* r5 = sres + 192 + 5 * lane;
        r5[0] = u0; r5[1] = u1; r5[2] = u2; r5[3] = u3; r5[4] = u4;
    }

    // ---- LayerNorm over first 128 (shfl latency overlaps the STS drain) ----
    float s  = q.x + q.y + q.z + q.w;
    float ss = q.x * q.x + q.y * q.y + q.z * q.z + q.w * q.w;
#pragma unroll
    for (int o = 16; o > 0; o >>= 1) {
        s  += __shfl_xor_sync(0xffffffffu, s,  o);
        ss += __shfl_xor_sync(0xffffffffu, ss, o);
    }
    const float mean = s * (1.0f / 128.0f);
    const float var  = ss * (1.0f / 128.0f) - mean * mean;
    const float rstd = rsqrtf(var + 1e-5f);
    {
        const int c = lane * 4;
        float4 r;
        r.x = (q.x - mean) * rstd * __ldg(w + c + 0) + __ldg(bias + c + 0);
        r.y = (q.y - mean) * rstd * __ldg(w + c + 1) + __ldg(bias + c + 1);
        r.z = (q.z - mean) * rstd * __ldg(w + c + 2) + __ldg(bias + c + 2);
        r.w = (q.w - mean) * rstd * __ldg(w + c + 3) + __ldg(bias + c + 3);
        // default writeback store: let L2 batch the write stream
        reinterpret_cast<float4*>(dst)[lane] = r;
    }

    __syncwarp();

    // ---- cooperative, fully-coalesced float4 store of segment results (writeback) ----
    float4* dst4 = reinterpret_cast<float4*>(dst);
    dst4[32 + lane] = sres4[warp][lane];
    dst4[64 + lane] = sres4[warp][lane + 32];
    if (lane < SEGV - 64)
        dst4[96 + lane] = sres4[warp][lane + 64];
}

extern "C" void kernel_launch(void* const* d_in, const int* in_sizes, int n_in,
                              void* d_out, int out_size)
{
    const float* x    = (const float*)d_in[0];
    const float* w    = (const float*)d_in[1];
    const float* bias = (const float*)d_in[2];
    float* out        = (float*)d_out;

    int n = in_sizes[0] / DIM;
    int blocks = (n + WPB - 1) / WPB;
    eqln_kernel<<<blocks, WPB * 32>>>(x, w, bias, out, n);
}

// round 15
// speedup vs baseline: 1.0218x; 1.0218x over previous
#include <cuda_runtime.h>

#define DIM  480
#define WPB  8          // warps (rows) per block
#define SEGV 88         // segment-region float4 per row

__global__ __launch_bounds__(WPB * 32) void eqln_kernel(
    const float* __restrict__ x,
    const float* __restrict__ w,
    const float* __restrict__ bias,
    float* __restrict__ out,
    int n)
{
    __shared__ float4 sres4[WPB][SEGV];    // staged RESULTS only (coalesced store)

    const int warp = threadIdx.x >> 5;
    const int lane = threadIdx.x & 31;
    const int row  = blockIdx.x * WPB + warp;
    if (row >= n) return;

    float* sres = reinterpret_cast<float*>(sres4[warp]);
    const size_t off = (size_t)row * DIM;
    const float* src = x + off;
    float* dst       = out + off;

    // ---- front-batch ALL loads (9 per lane; lane-private segment data) ----
    float4 q = __ldcs(reinterpret_cast<const float4*>(src) + lane);   // floats 4l..4l+3

    // 3-seg region: lane owns segs 2l,2l+1 = floats 128+6l..+5 (8B-aligned float2 x3)
    const float2* p3 = reinterpret_cast<const float2*>(src + 128 + 6 * lane);
    float2 t0 = __ldcs(p3 + 0);
    float2 t1 = __ldcs(p3 + 1);
    float2 t2 = __ldcs(p3 + 2);

    // 5-seg region: lane owns seg l = floats 320+5l..+4
    const float* p5 = src + 320 + 5 * lane;
    float u0 = __ldcs(p5 + 0);
    float u1 = __ldcs(p5 + 1);
    float u2 = __ldcs(p5 + 2);
    float u3 = __ldcs(p5 + 3);
    float u4 = __ldcs(p5 + 4);

    // ---- segment norms in registers ----
    {   // seg 2l: t0.x t0.y t1.x
        float m  = (t0.x + t0.y + t1.x) * (1.0f / 3.0f);
        float da = t0.x - m, db = t0.y - m, dc = t1.x - m;
        float rv = rsqrtf((da * da + db * db + dc * dc) * (1.0f / 3.0f) + 1e-5f);
        t0.x = da * rv; t0.y = db * rv; t1.x = dc * rv;
    }
    {   // seg 2l+1: t1.y t2.x t2.y
        float m  = (t1.y + t2.x + t2.y) * (1.0f / 3.0f);
        float da = t1.y - m, db = t2.x - m, dc = t2.y - m;
        float rv = rsqrtf((da * da + db * db + dc * dc) * (1.0f / 3.0f) + 1e-5f);
        t1.y = da * rv; t2.x = db * rv; t2.y = dc * rv;
    }
    {   // seg l of 5
        float m  = (u0 + u1 + u2 + u3 + u4) * 0.2f;
        float da = u0 - m, db = u1 - m, dc = u2 - m, dd = u3 - m, de = u4 - m;
        float rv = rsqrtf((da * da + db * db + dc * dc + dd * dd + de * de) * 0.2f + 1e-5f);
        u0 = da * rv; u1 = db * rv; u2 = dc * rv; u3 = dd * rv; u4 = de * rv;
    }

    // ---- stage results into smem (conflict-light) ----
    {
        float2* r3 = reinterpret_cast<float2*>(sres + 6 * lane);
        r3[0] = t0; r3[1] = t1; r3[2] = t2;
        float* r5 = sres + 192 + 5 * lane;
        r5[0] = u0; r5[1] = u1; r5[2] = u2; r5[3] = u3; r5[4] = u4;
    }

    // ---- LayerNorm over first 128 (shfl latency overlaps the STS drain) ----
    float s  = q.x + q.y + q.z + q.w;
    float ss = q.x * q.x + q.y * q.y + q.z * q.z + q.w * q.w;
#pragma unroll
    for (int o = 16; o > 0; o >>= 1) {
        s  += __shfl_xor_sync(0xffffffffu, s,  o);
        ss += __shfl_xor_sync(0xffffffffu, ss, o);
    }
    const float mean = s * (1.0f / 128.0f);
    const float var  = ss * (1.0f / 128.0f) - mean * mean;
    const float rstd = rsqrtf(var + 1e-5f);
    {
        const int c = lane * 4;
        float4 r;
        r.x = (q.x - mean) * rstd * __ldg(w + c + 0) + __ldg(bias + c + 0);
        r.y = (q.y - mean) * rstd * __ldg(w + c + 1) + __ldg(bias + c + 1);
        r.z = (q.z - mean) * rstd * __ldg(w + c + 2) + __ldg(bias + c + 2);
        r.w = (q.w - mean) * rstd * __ldg(w + c + 3) + __ldg(bias + c + 3);
        __stcs(reinterpret_cast<float4*>(dst) + lane, r);   // coalesced 512B/warp
    }

    __syncwarp();

    // ---- cooperative, fully-coalesced float4 store of segment results ----
    float4* dst4 = reinterpret_cast<float4*>(dst);
    __stcs(dst4 + 32 + lane, sres4[warp][lane]);
    __stcs(dst4 + 64 + lane, sres4[warp][lane + 32]);
    if (lane < SEGV - 64)
        __stcs(dst4 + 96 + lane, sres4[warp][lane + 64]);
}

extern "C" void kernel_launch(void* const* d_in, const int* in_sizes, int n_in,
                              void* d_out, int out_size)
{
    const float* x    = (const float*)d_in[0];
    const float* w    = (const float*)d_in[1];
    const float* bias = (const float*)d_in[2];
    float* out        = (float*)d_out;

    int n = in_sizes[0] / DIM;
    int blocks = (n + WPB - 1) / WPB;
    eqln_kernel<<<blocks, WPB * 32>>>(x, w, bias, out, n);
}